// round 14
// baseline (speedup 1.0000x reference)
#include <cuda_runtime.h>

// FPN Pooler: multi-level ROIAlign, direct scattered-gather.
// Block-uniform fast path: when every bin's 4 x-corners fit in an aligned
// 8-float window (span check over all 7 pw from smem tables -> uniform),
// each bin-row is read with 2x LDG.128 instead of 4x LDG.32, halving L1
// wavefront work (wf ~ load-instruction count x distinct lines).
// Fallback: R8 scalar path (block-uniform too -> no divergence).
// feats NCHW f32: f0 [2,256,200,200], f1 [2,256,100,100], f2 [2,256,50,50], f3 [2,256,25,25]
// boxes [1000,4], img_ids [1000] -> out [1000,256,7,7] f32

#define P 14           // OUT*SR samples per axis
#define BLOCK 224      // 7 warps; 196 active threads (196 = 4*49)
#define ACT 196
#define QCH 64         // channels per block (quarter)
#define ITERS 16       // QCH / 4 channel-substreams

__global__ __launch_bounds__(BLOCK, 5) void pooler_kernel(
    const float* __restrict__ f0, const float* __restrict__ f1,
    const float* __restrict__ f2, const float* __restrict__ f3,
    const float* __restrict__ boxes, const int* __restrict__ img_ids,
    float* __restrict__ out)
{
    const int bx  = blockIdx.x;
    const int n   = bx >> 2;
    const int q   = bx & 3;           // channel quarter
    const int tid = threadIdx.x;

    __shared__ int   s_ro0[P], s_ro1[P];   // y0*W, y1*W
    __shared__ int   s_x0[P],  s_x1[P];
    __shared__ float s_ay0[P], s_ay1[P];   // 0.25 * vy * {hy, ly}
    __shared__ float s_ax0[P], s_ax1[P];   // vx * {hx, lx}
    __shared__ const float* s_base;
    __shared__ int s_HW, s_W;

    // ---- per-box geometry (x by tid 0..13, y by tid 16..29, scalars by 32) ----
    {
        const float bx1 = boxes[4*n+0], by1 = boxes[4*n+1];
        const float bx2 = boxes[4*n+2], by2 = boxes[4*n+3];
        const float sq  = sqrtf((bx2 - bx1) * (by2 - by1));
        float lf = floorf(4.0f + log2f(sq / 224.0f + 1e-6f));
        lf = fminf(fmaxf(lf, 2.0f), 5.0f);
        const int lvl = (int)lf - 2;

        int H, W; float scale; const float* fp;
        switch (lvl) {
            case 0:  H = 200; W = 200; scale = 0.25f;    fp = f0; break;
            case 1:  H = 100; W = 100; scale = 0.125f;   fp = f1; break;
            case 2:  H = 50;  W = 50;  scale = 0.0625f;  fp = f2; break;
            default: H = 25;  W = 25;  scale = 0.03125f; fp = f3; break;
        }
        const int HW = H * W;

        const float rx1 = bx1 * scale, ry1 = by1 * scale;
        const float roi_w = fmaxf(bx2 * scale - rx1, 1.0f);
        const float roi_h = fmaxf(by2 * scale - ry1, 1.0f);
        const float bw = roi_w * (1.0f / 7.0f);
        const float bh = roi_h * (1.0f / 7.0f);

        if (tid < P) {
            const int i = tid, p = i >> 1, r = i & 1;
            const float xg = rx1 + (float)p * bw + ((float)r + 0.5f) * bw * 0.5f;
            const float vx = (xg >= -1.0f && xg <= (float)W) ? 1.0f : 0.0f;
            float x = fminf(fmaxf(xg, 0.0f), (float)(W - 1));
            const int x0 = (int)x;                 // x>=0: trunc == floor
            s_x0[i] = x0;
            s_x1[i] = min(x0 + 1, W - 1);
            const float lx = x - (float)x0;
            s_ax0[i] = vx * (1.0f - lx);
            s_ax1[i] = vx * lx;
        } else if (tid >= 16 && tid < 16 + P) {
            const int i = tid - 16, p = i >> 1, r = i & 1;
            const float yg = ry1 + (float)p * bh + ((float)r + 0.5f) * bh * 0.5f;
            const float vy = (yg >= -1.0f && yg <= (float)H) ? 0.25f : 0.0f;  // fold mean
            float y = fminf(fmaxf(yg, 0.0f), (float)(H - 1));
            const int y0 = (int)y;
            s_ro0[i] = y0 * W;
            s_ro1[i] = min(y0 + 1, H - 1) * W;
            const float ly = y - (float)y0;
            s_ay0[i] = vy * (1.0f - ly);
            s_ay1[i] = vy * ly;
        } else if (tid == 32) {
            const int img = __ldg(img_ids + n);
            s_base = fp + (size_t)img * 256 * HW;
            s_HW   = HW;
            s_W    = W;
        }
    }
    __syncthreads();

    if (tid >= ACT) return;

    const int W  = s_W;
    const int HW = s_HW;

    // ---- block-uniform fast-path eligibility (same smem data -> same result
    //      in every thread; no divergence) ----
    bool vecok = (W >= 100);
    #pragma unroll
    for (int i = 0; i < 7; ++i) {
        const int xa  = s_x0[2*i];
        const int xb1 = s_x1[2*i + 1];
        const int aw  = min(xa & ~3, W - 8);
        vecok = vecok && (xb1 - aw <= 7);
    }

    // ---- fixed-bin geometry in registers (once per block) ----
    const int csub = tid / 49;          // 0..3
    const int bin  = tid - csub * 49;
    const int ph = bin / 7, pw = bin - ph * 7;
    const int iyA = 2*ph, iyB = iyA + 1;
    const int ixA = 2*pw, ixB = ixA + 1;

    const int r0 = s_ro0[iyA], r1 = s_ro1[iyA];
    const int r2 = s_ro0[iyB], r3 = s_ro1[iyB];
    const int xA0 = s_x0[ixA], xA1 = s_x1[ixA];
    const int xB0 = s_x0[ixB], xB1 = s_x1[ixB];
    const float a0 = s_ay0[iyA], a1 = s_ay1[iyA];
    const float a2 = s_ay0[iyB], a3 = s_ay1[iyB];
    const float b0 = s_ax0[ixA], b1 = s_ax1[ixA];
    const float b2 = s_ax0[ixB], b3 = s_ax1[ixB];

    const size_t chStep = (size_t)4 * HW;
    // channel = q*64 + csub + 4*i
    const float* fc = s_base + (size_t)(q * QCH + csub) * HW;
    float* outp = out + (size_t)n * 12544 + (size_t)q * (QCH * 49) + tid;

    if (vecok) {
        // ===== fast path: 2x LDG.128 per bin-row (8 loads/channel) =====
        const int a = min(xA0 & ~3, W - 8);   // 4-aligned, window inside row
        const int jA0 = xA0 - a, jA1 = xA1 - a;
        const int jB0 = xB0 - a, jB1 = xB1 - a;

        float w[8];
        #pragma unroll
        for (int j = 0; j < 8; ++j) {
            float t = 0.0f;
            t += (j == jA0) ? b0 : 0.0f;
            t += (j == jA1) ? b1 : 0.0f;
            t += (j == jB0) ? b2 : 0.0f;
            t += (j == jB1) ? b3 : 0.0f;
            w[j] = t;
        }

        const int o0 = r0 + a, o1 = r1 + a, o2 = r2 + a, o3 = r3 + a;

        #pragma unroll 1
        for (int i = 0; i < ITERS; ++i) {
            const float4 u0 = __ldg((const float4*)(fc + o0));
            const float4 v0 = __ldg((const float4*)(fc + o0) + 1);
            const float4 u1 = __ldg((const float4*)(fc + o1));
            const float4 v1 = __ldg((const float4*)(fc + o1) + 1);
            const float4 u2 = __ldg((const float4*)(fc + o2));
            const float4 v2 = __ldg((const float4*)(fc + o2) + 1);
            const float4 u3 = __ldg((const float4*)(fc + o3));
            const float4 v3 = __ldg((const float4*)(fc + o3) + 1);

            float t0 = w[0]*u0.x + w[1]*u0.y + w[2]*u0.z + w[3]*u0.w
                     + w[4]*v0.x + w[5]*v0.y + w[6]*v0.z + w[7]*v0.w;
            float t1 = w[0]*u1.x + w[1]*u1.y + w[2]*u1.z + w[3]*u1.w
                     + w[4]*v1.x + w[5]*v1.y + w[6]*v1.z + w[7]*v1.w;
            float t2 = w[0]*u2.x + w[1]*u2.y + w[2]*u2.z + w[3]*u2.w
                     + w[4]*v2.x + w[5]*v2.y + w[6]*v2.z + w[7]*v2.w;
            float t3 = w[0]*u3.x + w[1]*u3.y + w[2]*u3.z + w[3]*u3.w
                     + w[4]*v3.x + w[5]*v3.y + w[6]*v3.z + w[7]*v3.w;

            *outp = a0*t0 + a1*t1 + a2*t2 + a3*t3;

            fc += chStep;
            outp += ACT;
        }
    } else {
        // ===== scalar path (R8 baseline): elongated boxes, W=50/25 =====
        const int i00 = r0+xA0, i01 = r0+xA1, i02 = r0+xB0, i03 = r0+xB1;
        const int i10 = r1+xA0, i11 = r1+xA1, i12 = r1+xB0, i13 = r1+xB1;
        const int i20 = r2+xA0, i21 = r2+xA1, i22 = r2+xB0, i23 = r2+xB1;
        const int i30 = r3+xA0, i31 = r3+xA1, i32 = r3+xB0, i33 = r3+xB1;

        #pragma unroll 1
        for (int i = 0; i < ITERS; ++i) {
            const float p00 = __ldg(fc + i00), p01 = __ldg(fc + i01);
            const float p02 = __ldg(fc + i02), p03 = __ldg(fc + i03);
            const float p10 = __ldg(fc + i10), p11 = __ldg(fc + i11);
            const float p12 = __ldg(fc + i12), p13 = __ldg(fc + i13);
            const float p20 = __ldg(fc + i20), p21 = __ldg(fc + i21);
            const float p22 = __ldg(fc + i22), p23 = __ldg(fc + i23);
            const float p30 = __ldg(fc + i30), p31 = __ldg(fc + i31);
            const float p32 = __ldg(fc + i32), p33 = __ldg(fc + i33);

            float s0 = b0*p00 + b1*p01 + b2*p02 + b3*p03;
            float s1 = b0*p10 + b1*p11 + b2*p12 + b3*p13;
            float s2 = b0*p20 + b1*p21 + b2*p22 + b3*p23;
            float s3 = b0*p30 + b1*p31 + b2*p32 + b3*p33;

            *outp = a0*s0 + a1*s1 + a2*s2 + a3*s3;

            fc += chStep;
            outp += ACT;
        }
    }
}

extern "C" void kernel_launch(void* const* d_in, const int* in_sizes, int n_in,
                              void* d_out, int out_size)
{
    const float* f0    = (const float*)d_in[0];
    const float* f1    = (const float*)d_in[1];
    const float* f2    = (const float*)d_in[2];
    const float* f3    = (const float*)d_in[3];
    const float* boxes = (const float*)d_in[4];
    const int*   imgs  = (const int*)d_in[5];
    float* out = (float*)d_out;

    const int N = in_sizes[4] / 4;   // 1000 boxes
    pooler_kernel<<<N * 4, BLOCK>>>(f0, f1, f2, f3, boxes, imgs, out);
}

// round 15
// speedup vs baseline: 1.0494x; 1.0494x over previous
#include <cuda_runtime.h>

// FPN Pooler: multi-level ROIAlign, sample-grid lane layout.
// Thread = sample point (ix, iy) of the 14x14 grid; warp w owns iy {2w, 2w+1},
// lane = ix + 16*iy_sub. One warp-LDG per corner touches only 2 feature rows
// x ~4 sectors (samples are consecutive columns) instead of scattering over
// the whole window like bin-per-thread layout. Bin = butterfly reduction
// (shfl_xor 1, then 16) of its 4 weighted samples.
// feats NCHW f32: f0 [2,256,200,200], f1 [2,256,100,100], f2 [2,256,50,50], f3 [2,256,25,25]
// boxes [1000,4], img_ids [1000] -> out [1000,256,7,7] f32

#define P 14           // OUT*SR samples per axis
#define BLOCK 224      // 7 warps = 14 iy rows x 16 lanes
#define QCH 64         // channels per block (quarter)

__global__ __launch_bounds__(BLOCK, 5) void pooler_kernel(
    const float* __restrict__ f0, const float* __restrict__ f1,
    const float* __restrict__ f2, const float* __restrict__ f3,
    const float* __restrict__ boxes, const int* __restrict__ img_ids,
    float* __restrict__ out)
{
    const int bx  = blockIdx.x;
    const int n   = bx >> 2;
    const int q   = bx & 3;           // channel quarter
    const int tid = threadIdx.x;

    __shared__ int   s_ro0[P], s_ro1[P];   // y0*W, y1*W
    __shared__ int   s_x0[P],  s_x1[P];
    __shared__ float s_ay0[P], s_ay1[P];   // 0.25 * vy * {hy, ly}
    __shared__ float s_ax0[P], s_ax1[P];   // vx * {hx, lx}
    __shared__ const float* s_base;
    __shared__ int s_HW;

    // ---- per-box geometry (x by tid 0..13, y by tid 16..29, scalars by 32) ----
    {
        const float bx1 = boxes[4*n+0], by1 = boxes[4*n+1];
        const float bx2 = boxes[4*n+2], by2 = boxes[4*n+3];
        const float sq  = sqrtf((bx2 - bx1) * (by2 - by1));
        float lf = floorf(4.0f + log2f(sq / 224.0f + 1e-6f));
        lf = fminf(fmaxf(lf, 2.0f), 5.0f);
        const int lvl = (int)lf - 2;

        int H, W; float scale; const float* fp;
        switch (lvl) {
            case 0:  H = 200; W = 200; scale = 0.25f;    fp = f0; break;
            case 1:  H = 100; W = 100; scale = 0.125f;   fp = f1; break;
            case 2:  H = 50;  W = 50;  scale = 0.0625f;  fp = f2; break;
            default: H = 25;  W = 25;  scale = 0.03125f; fp = f3; break;
        }
        const int HW = H * W;

        const float rx1 = bx1 * scale, ry1 = by1 * scale;
        const float roi_w = fmaxf(bx2 * scale - rx1, 1.0f);
        const float roi_h = fmaxf(by2 * scale - ry1, 1.0f);
        const float bw = roi_w * (1.0f / 7.0f);
        const float bh = roi_h * (1.0f / 7.0f);

        if (tid < P) {
            const int i = tid, p = i >> 1, r = i & 1;
            const float xg = rx1 + (float)p * bw + ((float)r + 0.5f) * bw * 0.5f;
            const float vx = (xg >= -1.0f && xg <= (float)W) ? 1.0f : 0.0f;
            float x = fminf(fmaxf(xg, 0.0f), (float)(W - 1));
            const int x0 = (int)x;                 // x>=0: trunc == floor
            s_x0[i] = x0;
            s_x1[i] = min(x0 + 1, W - 1);
            const float lx = x - (float)x0;
            s_ax0[i] = vx * (1.0f - lx);
            s_ax1[i] = vx * lx;
        } else if (tid >= 16 && tid < 16 + P) {
            const int i = tid - 16, p = i >> 1, r = i & 1;
            const float yg = ry1 + (float)p * bh + ((float)r + 0.5f) * bh * 0.5f;
            const float vy = (yg >= -1.0f && yg <= (float)H) ? 0.25f : 0.0f;  // fold mean
            float y = fminf(fmaxf(yg, 0.0f), (float)(H - 1));
            const int y0 = (int)y;
            s_ro0[i] = y0 * W;
            s_ro1[i] = min(y0 + 1, H - 1) * W;
            const float ly = y - (float)y0;
            s_ay0[i] = vy * (1.0f - ly);
            s_ay1[i] = vy * ly;
        } else if (tid == 32) {
            const int img = __ldg(img_ids + n);
            s_base = fp + (size_t)img * 256 * HW;
            s_HW   = HW;
        }
    }
    __syncthreads();

    // ---- sample-role assignment (all 224 threads stay active for shfl) ----
    const int warp = tid >> 5, lane = tid & 31;
    const int iy = 2 * warp + (lane >> 4);      // 0..13
    const int ix = min(lane & 15, 13);          // lanes 14,15 duplicate ix=13 (results unused)

    const int r0 = s_ro0[iy], r1 = s_ro1[iy];
    const int c0 = s_x0[ix],  c1 = s_x1[ix];
    const float wy0 = s_ay0[iy], wy1 = s_ay1[iy];
    const float wx0 = s_ax0[ix], wx1 = s_ax1[ix];

    const int o00 = r0 + c0, o01 = r0 + c1;
    const int o10 = r1 + c0, o11 = r1 + c1;

    const int HW = s_HW;
    const float* fc = s_base + (size_t)(q * QCH) * HW;
    // writer lane: even ix, low half -> bin(warp, ix/2)
    const bool writer = (lane < 14) && !(lane & 1);
    float* outw = out + (size_t)n * 12544 + (size_t)q * (QCH * 49)
                + warp * 7 + (lane >> 1);

    #pragma unroll 1
    for (int ch = 0; ch < QCH; ch += 4) {
        const float* fA = fc + (size_t)ch * HW;
        const float* fB = fA + HW;
        const float* fC = fB + HW;
        const float* fD = fC + HW;

        // 16 independent loads (4 channels x 4 corners)
        const float pA00 = __ldg(fA + o00), pA01 = __ldg(fA + o01);
        const float pA10 = __ldg(fA + o10), pA11 = __ldg(fA + o11);
        const float pB00 = __ldg(fB + o00), pB01 = __ldg(fB + o01);
        const float pB10 = __ldg(fB + o10), pB11 = __ldg(fB + o11);
        const float pC00 = __ldg(fC + o00), pC01 = __ldg(fC + o01);
        const float pC10 = __ldg(fC + o10), pC11 = __ldg(fC + o11);
        const float pD00 = __ldg(fD + o00), pD01 = __ldg(fD + o01);
        const float pD10 = __ldg(fD + o10), pD11 = __ldg(fD + o11);

        // weighted bilinear sample values (0.25 * valid folded in wy/wx)
        float vA = wy0 * (wx0*pA00 + wx1*pA01) + wy1 * (wx0*pA10 + wx1*pA11);
        float vB = wy0 * (wx0*pB00 + wx1*pB01) + wy1 * (wx0*pB10 + wx1*pB11);
        float vC = wy0 * (wx0*pC00 + wx1*pC01) + wy1 * (wx0*pC10 + wx1*pC11);
        float vD = wy0 * (wx0*pD00 + wx1*pD01) + wy1 * (wx0*pD10 + wx1*pD11);

        // butterfly: combine x-pair (lanes 2pw,2pw+1), then y-pair (lane +16)
        vA += __shfl_xor_sync(0xffffffffu, vA, 1);
        vB += __shfl_xor_sync(0xffffffffu, vB, 1);
        vC += __shfl_xor_sync(0xffffffffu, vC, 1);
        vD += __shfl_xor_sync(0xffffffffu, vD, 1);
        vA += __shfl_xor_sync(0xffffffffu, vA, 16);
        vB += __shfl_xor_sync(0xffffffffu, vB, 16);
        vC += __shfl_xor_sync(0xffffffffu, vC, 16);
        vD += __shfl_xor_sync(0xffffffffu, vD, 16);

        if (writer) {
            outw[(ch + 0) * 49] = vA;
            outw[(ch + 1) * 49] = vB;
            outw[(ch + 2) * 49] = vC;
            outw[(ch + 3) * 49] = vD;
        }
    }
}

extern "C" void kernel_launch(void* const* d_in, const int* in_sizes, int n_in,
                              void* d_out, int out_size)
{
    const float* f0    = (const float*)d_in[0];
    const float* f1    = (const float*)d_in[1];
    const float* f2    = (const float*)d_in[2];
    const float* f3    = (const float*)d_in[3];
    const float* boxes = (const float*)d_in[4];
    const int*   imgs  = (const int*)d_in[5];
    float* out = (float*)d_out;

    const int N = in_sizes[4] / 4;   // 1000 boxes
    pooler_kernel<<<N * 4, BLOCK>>>(f0, f1, f2, f3, boxes, imgs, out);
}

// round 16
// speedup vs baseline: 2.0129x; 1.9183x over previous
#include <cuda_runtime.h>

// FPN Pooler: multi-level ROIAlign, sample-grid lane layout + software pipeline.
// Thread = sample point (ix, iy); warp w owns iy {2w, 2w+1}, lane = ix + 16*iy_sub.
// Corner warp-LDGs touch only ~2 feature rows x ~4 sectors. Bin = butterfly
// (shfl_xor 1, 16). Channel batches of 4 are double-buffered so batch i+1's
// 16 independent LDGs overlap batch i's FMA/shuffle/store chain.
// feats NCHW f32: f0 [2,256,200,200], f1 [2,256,100,100], f2 [2,256,50,50], f3 [2,256,25,25]
// boxes [1000,4], img_ids [1000] -> out [1000,256,7,7] f32

#define P 14           // OUT*SR samples per axis
#define BLOCK 224      // 7 warps = 14 iy rows x 16 lanes
#define QCH 64         // channels per block (quarter)

__global__ __launch_bounds__(BLOCK, 4) void pooler_kernel(
    const float* __restrict__ f0, const float* __restrict__ f1,
    const float* __restrict__ f2, const float* __restrict__ f3,
    const float* __restrict__ boxes, const int* __restrict__ img_ids,
    float* __restrict__ out)
{
    const int bx  = blockIdx.x;
    const int n   = bx >> 2;
    const int q   = bx & 3;           // channel quarter
    const int tid = threadIdx.x;

    __shared__ int   s_ro0[P], s_ro1[P];   // y0*W, y1*W
    __shared__ int   s_x0[P],  s_x1[P];
    __shared__ float s_ay0[P], s_ay1[P];   // 0.25 * vy * {hy, ly}
    __shared__ float s_ax0[P], s_ax1[P];   // vx * {hx, lx}
    __shared__ const float* s_base;
    __shared__ int s_HW;

    // ---- per-box geometry (x by tid 0..13, y by tid 16..29, scalars by 32) ----
    {
        const float bx1 = boxes[4*n+0], by1 = boxes[4*n+1];
        const float bx2 = boxes[4*n+2], by2 = boxes[4*n+3];
        const float sq  = sqrtf((bx2 - bx1) * (by2 - by1));
        float lf = floorf(4.0f + log2f(sq / 224.0f + 1e-6f));
        lf = fminf(fmaxf(lf, 2.0f), 5.0f);
        const int lvl = (int)lf - 2;

        int H, W; float scale; const float* fp;
        switch (lvl) {
            case 0:  H = 200; W = 200; scale = 0.25f;    fp = f0; break;
            case 1:  H = 100; W = 100; scale = 0.125f;   fp = f1; break;
            case 2:  H = 50;  W = 50;  scale = 0.0625f;  fp = f2; break;
            default: H = 25;  W = 25;  scale = 0.03125f; fp = f3; break;
        }
        const int HW = H * W;

        const float rx1 = bx1 * scale, ry1 = by1 * scale;
        const float roi_w = fmaxf(bx2 * scale - rx1, 1.0f);
        const float roi_h = fmaxf(by2 * scale - ry1, 1.0f);
        const float bw = roi_w * (1.0f / 7.0f);
        const float bh = roi_h * (1.0f / 7.0f);

        if (tid < P) {
            const int i = tid, p = i >> 1, r = i & 1;
            const float xg = rx1 + (float)p * bw + ((float)r + 0.5f) * bw * 0.5f;
            const float vx = (xg >= -1.0f && xg <= (float)W) ? 1.0f : 0.0f;
            float x = fminf(fmaxf(xg, 0.0f), (float)(W - 1));
            const int x0 = (int)x;                 // x>=0: trunc == floor
            s_x0[i] = x0;
            s_x1[i] = min(x0 + 1, W - 1);
            const float lx = x - (float)x0;
            s_ax0[i] = vx * (1.0f - lx);
            s_ax1[i] = vx * lx;
        } else if (tid >= 16 && tid < 16 + P) {
            const int i = tid - 16, p = i >> 1, r = i & 1;
            const float yg = ry1 + (float)p * bh + ((float)r + 0.5f) * bh * 0.5f;
            const float vy = (yg >= -1.0f && yg <= (float)H) ? 0.25f : 0.0f;  // fold mean
            float y = fminf(fmaxf(yg, 0.0f), (float)(H - 1));
            const int y0 = (int)y;
            s_ro0[i] = y0 * W;
            s_ro1[i] = min(y0 + 1, H - 1) * W;
            const float ly = y - (float)y0;
            s_ay0[i] = vy * (1.0f - ly);
            s_ay1[i] = vy * ly;
        } else if (tid == 32) {
            const int img = __ldg(img_ids + n);
            s_base = fp + (size_t)img * 256 * HW;
            s_HW   = HW;
        }
    }
    __syncthreads();

    // ---- sample-role assignment (all 224 threads stay active for shfl) ----
    const int warp = tid >> 5, lane = tid & 31;
    const int iy = 2 * warp + (lane >> 4);      // 0..13
    const int ix = min(lane & 15, 13);          // lanes 14,15 duplicate ix=13 (unused)

    const int r0 = s_ro0[iy], r1 = s_ro1[iy];
    const int c0 = s_x0[ix],  c1 = s_x1[ix];
    const float wy0 = s_ay0[iy], wy1 = s_ay1[iy];
    const float wx0 = s_ax0[ix], wx1 = s_ax1[ix];

    const int o00 = r0 + c0, o01 = r0 + c1;
    const int o10 = r1 + c0, o11 = r1 + c1;

    const int HW = s_HW;
    const float* fc = s_base + (size_t)(q * QCH) * HW;
    const bool writer = (lane < 14) && !(lane & 1);
    float* outw = out + (size_t)n * 12544 + (size_t)q * (QCH * 49)
                + warp * 7 + (lane >> 1);

    // load 16 corners (4 channels x 4) into dst[16]
    auto load16 = [&](float* dst, const float* fA) {
        const float* fB = fA + HW;
        const float* fC = fB + HW;
        const float* fD = fC + HW;
        dst[0]  = __ldg(fA + o00); dst[1]  = __ldg(fA + o01);
        dst[2]  = __ldg(fA + o10); dst[3]  = __ldg(fA + o11);
        dst[4]  = __ldg(fB + o00); dst[5]  = __ldg(fB + o01);
        dst[6]  = __ldg(fB + o10); dst[7]  = __ldg(fB + o11);
        dst[8]  = __ldg(fC + o00); dst[9]  = __ldg(fC + o01);
        dst[10] = __ldg(fC + o10); dst[11] = __ldg(fC + o11);
        dst[12] = __ldg(fD + o00); dst[13] = __ldg(fD + o01);
        dst[14] = __ldg(fD + o10); dst[15] = __ldg(fD + o11);
    };

    // weighted bilinear + butterfly + store for a 4-channel batch
    auto process = [&](const float* pz, int ch) {
        float vA = wy0 * (wx0*pz[0]  + wx1*pz[1])  + wy1 * (wx0*pz[2]  + wx1*pz[3]);
        float vB = wy0 * (wx0*pz[4]  + wx1*pz[5])  + wy1 * (wx0*pz[6]  + wx1*pz[7]);
        float vC = wy0 * (wx0*pz[8]  + wx1*pz[9])  + wy1 * (wx0*pz[10] + wx1*pz[11]);
        float vD = wy0 * (wx0*pz[12] + wx1*pz[13]) + wy1 * (wx0*pz[14] + wx1*pz[15]);

        vA += __shfl_xor_sync(0xffffffffu, vA, 1);
        vB += __shfl_xor_sync(0xffffffffu, vB, 1);
        vC += __shfl_xor_sync(0xffffffffu, vC, 1);
        vD += __shfl_xor_sync(0xffffffffu, vD, 1);
        vA += __shfl_xor_sync(0xffffffffu, vA, 16);
        vB += __shfl_xor_sync(0xffffffffu, vB, 16);
        vC += __shfl_xor_sync(0xffffffffu, vC, 16);
        vD += __shfl_xor_sync(0xffffffffu, vD, 16);

        if (writer) {
            outw[(ch + 0) * 49] = vA;
            outw[(ch + 1) * 49] = vB;
            outw[(ch + 2) * 49] = vC;
            outw[(ch + 3) * 49] = vD;
        }
    };

    // ---- software-pipelined main loop: 2-stage ping-pong, batches of 4 ch ----
    float bufA[16], bufB[16];
    load16(bufA, fc);                      // batch 0

    #pragma unroll 1
    for (int ch = 0; ch < QCH; ch += 8) {
        load16(bufB, fc + (size_t)(ch + 4) * HW);   // batch i+1 in flight
        process(bufA, ch);                          // overlap with bufB loads
        if (ch + 8 < QCH)
            load16(bufA, fc + (size_t)(ch + 8) * HW); // batch i+2 in flight
        process(bufB, ch + 4);
    }
}

extern "C" void kernel_launch(void* const* d_in, const int* in_sizes, int n_in,
                              void* d_out, int out_size)
{
    const float* f0    = (const float*)d_in[0];
    const float* f1    = (const float*)d_in[1];
    const float* f2    = (const float*)d_in[2];
    const float* f3    = (const float*)d_in[3];
    const float* boxes = (const float*)d_in[4];
    const int*   imgs  = (const int*)d_in[5];
    float* out = (float*)d_out;

    const int N = in_sizes[4] / 4;   // 1000 boxes
    pooler_kernel<<<N * 4, BLOCK>>>(f0, f1, f2, f3, boxes, imgs, out);
}